// round 13
// baseline (speedup 1.0000x reference)
#include <cuda_runtime.h>
#include <cuda_fp16.h>
#include <math.h>
#include <stdint.h>

#define NTOK 4096
#define DDIM 512
#define IDIM 2048
#define NEXP 8
#define SROW 72                // smem row stride in halves (144 B), k-chunk 64
#define STG 27648              // 192 rows * 144 B (both kernels)
#define SMEMB (2 * STG)        // 55296

// ===================== device scratch =====================
__device__ int g_expert[NTOK];
__device__ int g_pos[NTOK];
__device__ int g_perm[NTOK];
__device__ int g_cnt[NEXP];
__device__ int g_off[NEXP];
__device__ int g_tileE[64];
__device__ int g_tileRow[64];
__device__ int g_tileCnt[64];
__device__ int g_numTiles;

__device__ __half g_Hsh[(size_t)NTOK * IDIM];
__device__ __half g_Hrh[(size_t)NTOK * IDIM];

__device__ __half g_xh[(size_t)NTOK * DDIM];
__device__ __half g_sw1h[(size_t)IDIM * DDIM];
__device__ __half g_sw2h[(size_t)DDIM * IDIM];
__device__ __half g_w1h[(size_t)NEXP * IDIM * DDIM];
__device__ __half g_w3h[(size_t)NEXP * IDIM * DDIM];
__device__ __half g_w2h[(size_t)NEXP * DDIM * IDIM];

// ===================== PTX helpers =====================
__device__ __forceinline__ uint32_t smem_u32(const void* p) {
    uint32_t a;
    asm("{ .reg .u64 t; cvta.to.shared.u64 t, %1; cvt.u32.u64 %0, t; }" : "=r"(a) : "l"(p));
    return a;
}
#define CP16(dst, src) asm volatile("cp.async.cg.shared.global [%0], [%1], 16;" :: "r"(dst), "l"(src))
#define CP_COMMIT()    asm volatile("cp.async.commit_group;" ::: "memory")
#define CP_WAIT1()     asm volatile("cp.async.wait_group 1;" ::: "memory")

#define LDSM4(r0, r1, r2, r3, a) \
    asm volatile("ldmatrix.sync.aligned.m8n8.x4.shared.b16 {%0,%1,%2,%3}, [%4];" \
        : "=r"(r0), "=r"(r1), "=r"(r2), "=r"(r3) : "r"(a))

#define MMAH(d, A, B) \
    asm volatile("mma.sync.aligned.m16n8k16.row.col.f32.f16.f16.f32 " \
        "{%0,%1,%2,%3},{%4,%5,%6,%7},{%8,%9},{%0,%1,%2,%3};" \
        : "+f"((d)[0]), "+f"((d)[1]), "+f"((d)[2]), "+f"((d)[3]) \
        : "r"((A)[0]), "r"((A)[1]), "r"((A)[2]), "r"((A)[3]), "r"((B)[0]), "r"((B)[1]))

// ===================== conversion + gate setup =====================
#define C_X   524288L
#define C_SW1 786432L
#define C_SW2 1048576L
#define C_W1  3145728L
#define C_W3  5242880L
#define C_W2  7340032L

__global__ void cvt_all(const float* __restrict__ x,   const float* __restrict__ sw1,
                        const float* __restrict__ sw2, const float* __restrict__ w1,
                        const float* __restrict__ w3,  const float* __restrict__ w2) {
    if (blockIdx.x == 0 && threadIdx.x < NEXP) g_cnt[threadIdx.x] = 0;
    long i = (long)blockIdx.x * blockDim.x + threadIdx.x;
    if (i >= C_W2) return;
    const float* src; __half* dst; long off;
    if (i < C_X)        { src = x;   dst = g_xh;   off = i; }
    else if (i < C_SW1) { src = sw1; dst = g_sw1h; off = i - C_X; }
    else if (i < C_SW2) { src = sw2; dst = g_sw2h; off = i - C_SW1; }
    else if (i < C_W1)  { src = w1;  dst = g_w1h;  off = i - C_SW2; }
    else if (i < C_W3)  { src = w3;  dst = g_w3h;  off = i - C_W1; }
    else                { src = w2;  dst = g_w2h;  off = i - C_W3; }
    float4 v = reinterpret_cast<const float4*>(src)[off];
    reinterpret_cast<__half2*>(dst)[off * 2 + 0] = __floats2half2_rn(v.x, v.y);
    reinterpret_cast<__half2*>(dst)[off * 2 + 1] = __floats2half2_rn(v.z, v.w);
}

__global__ void gate_kernel(const float* __restrict__ x, const float* __restrict__ gw) {
    int warp = (int)((blockIdx.x * blockDim.x + threadIdx.x) >> 5);
    int lane = threadIdx.x & 31;
    if (warp >= NTOK) return;
    const float4* xr = reinterpret_cast<const float4*>(x + (size_t)warp * DDIM + lane * 16);
    float4 xv[4];
#pragma unroll
    for (int j = 0; j < 4; j++) xv[j] = xr[j];
    float best = -1e30f; int bi = 0;
#pragma unroll
    for (int e = 0; e < NEXP; e++) {
        const float4* gr = reinterpret_cast<const float4*>(gw + (size_t)e * DDIM + lane * 16);
        float s = 0.f;
#pragma unroll
        for (int j = 0; j < 4; j++) {
            float4 g = gr[j];
            s += xv[j].x * g.x + xv[j].y * g.y + xv[j].z * g.z + xv[j].w * g.w;
        }
#pragma unroll
        for (int o = 16; o > 0; o >>= 1) s += __shfl_xor_sync(0xffffffffu, s, o);
        if (s > best) { best = s; bi = e; }
    }
    if (lane == 0) {
        g_expert[warp] = bi;
        g_pos[warp] = atomicAdd(&g_cnt[bi], 1);
    }
}

__global__ void build_scatter_kernel() {
    if (threadIdx.x == 0) {
        int off = 0;
        for (int e = 0; e < NEXP; e++) { g_off[e] = off; off += g_cnt[e]; }
        int nt = 0;
        for (int e = 0; e < NEXP; e++)
            for (int r = 0; r < g_cnt[e]; r += 128) {
                g_tileE[nt] = e;
                g_tileRow[nt] = g_off[e] + r;
                g_tileCnt[nt] = min(128, g_cnt[e] - r);
                nt++;
            }
        g_numTiles = nt;
    }
    __syncthreads();
    for (int t = threadIdx.x; t < NTOK; t += blockDim.x)
        g_perm[g_off[g_expert[t]] + g_pos[t]] = t;
}

__device__ __forceinline__ float gelu_exact(float v) {
    return 0.5f * v * (1.0f + erff(v * 0.70710678118654752f));
}
__device__ __forceinline__ float silu_f(float v) {
    return v / (1.0f + expf(-v));
}

// ===================== UP: M128 x N32 dual-B, 256 thr, 3 CTAs/SM =====================
// grid (72, 64). bx<32: Hsh = gelu(x @ sw1^T). bx>=32: Hrh = silu(Xg@w1^T)*(Xg@w3^T).
// smem rows: A 0..127, B1 128..159, B3 160..191.
__global__ __launch_bounds__(256, 3)
void up_kernel()
{
    constexpr int NC = DDIM / 64;   // 8
    extern __shared__ __align__(16) char dyns[];
    __shared__ int s_rows[128];

    int bx = blockIdx.x, by = blockIdx.y;
    bool routed = (bx >= 32);
    int rowStart, rowCnt; int eid = 0;
    if (routed) {
        int bt = bx - 32;
        if (bt >= g_numTiles) return;
        eid = g_tileE[bt]; rowStart = g_tileRow[bt]; rowCnt = g_tileCnt[bt];
    } else {
        rowStart = bx * 128; rowCnt = 128;
    }

    const __half* B1 = routed ? (g_w1h + (size_t)eid * (IDIM * DDIM) + (size_t)(by * 32) * DDIM)
                              : (g_sw1h + (size_t)(by * 32) * DDIM);
    const __half* B3 = g_w3h + (size_t)eid * (IDIM * DDIM) + (size_t)(by * 32) * DDIM;

    int tid = threadIdx.x;
    if (tid < 128) {
        int r = routed ? min(tid, rowCnt - 1) : tid;
        s_rows[tid] = routed ? g_perm[rowStart + r] : (rowStart + r);
    }
    __syncthreads();

    uint32_t dynB = smem_u32(dyns);

    auto load_stage = [&](int c) {
        if (c < NC) {
            int kk = c * 64;
            uint32_t sb = dynB + (uint32_t)((c & 1) * STG);
#pragma unroll
            for (int i = 0; i < 6; i++) {
                int g = i * 256 + tid;        // 0..1535
                int row = g >> 3;             // 0..191
                int seg = (g & 7) * 8;
                if (row >= 160 && !routed) continue;
                uint32_t dst = sb + (uint32_t)(row * (SROW * 2) + seg * 2);
                const __half* src;
                if (row < 128)      src = g_xh + (size_t)s_rows[row] * DDIM + kk + seg;
                else if (row < 160) src = B1 + (size_t)(row - 128) * DDIM + kk + seg;
                else                src = B3 + (size_t)(row - 160) * DDIM + kk + seg;
                CP16(dst, src);
            }
        }
        CP_COMMIT();
    };

    int wid = tid >> 5, lane = tid & 31;
    int wm = (wid & 3) * 32;
    int wq = wid >> 2;              // 0 or 1: N halves
    int wn = wq * 16;
    int aRow = (lane & 7) + ((lane >> 3) & 1) * 8;
    int aCol = (lane >> 4) * 8;
    int bRow = (lane & 7) + ((lane >> 4) & 1) * 8;
    int bCol = ((lane >> 3) & 1) * 8;

    float acc1[2][2][4], acc3[2][2][4];
#pragma unroll
    for (int mf = 0; mf < 2; mf++)
#pragma unroll
        for (int nf = 0; nf < 2; nf++)
#pragma unroll
            for (int r = 0; r < 4; r++) { acc1[mf][nf][r] = 0.f; acc3[mf][nf][r] = 0.f; }

    load_stage(0);

    for (int c = 0; c < NC; ++c) {
        load_stage(c + 1);
        CP_WAIT1();
        __syncthreads();
        uint32_t sbA = dynB + (uint32_t)((c & 1) * STG);
        uint32_t sbB1 = sbA + 128 * (SROW * 2);
        uint32_t sbB3 = sbA + 160 * (SROW * 2);
#pragma unroll
        for (int kb = 0; kb < 64; kb += 16) {
            uint32_t ah[2][4], bh1[2][2], bh3[2][2];
            // issue ALL ldmatrix first, then all MMAs (overlap LDS latency with acc1 MMAs)
#pragma unroll
            for (int mf = 0; mf < 2; mf++) {
                uint32_t off = (uint32_t)(((wm + mf * 16 + aRow) * SROW + kb + aCol) * 2);
                LDSM4(ah[mf][0], ah[mf][1], ah[mf][2], ah[mf][3], sbA + off);
            }
            {
                uint32_t off = (uint32_t)(((wn + bRow) * SROW + kb + bCol) * 2);
                uint32_t r0, r1, r2, r3;
                LDSM4(r0, r1, r2, r3, sbB1 + off);
                bh1[0][0] = r0; bh1[0][1] = r1; bh1[1][0] = r2; bh1[1][1] = r3;
            }
            if (routed) {
                uint32_t off = (uint32_t)(((wn + bRow) * SROW + kb + bCol) * 2);
                uint32_t r0, r1, r2, r3;
                LDSM4(r0, r1, r2, r3, sbB3 + off);
                bh3[0][0] = r0; bh3[0][1] = r1; bh3[1][0] = r2; bh3[1][1] = r3;
            }
#pragma unroll
            for (int mf = 0; mf < 2; mf++)
#pragma unroll
                for (int nf = 0; nf < 2; nf++)
                    MMAH(acc1[mf][nf], ah[mf], bh1[nf]);
            if (routed) {
#pragma unroll
                for (int mf = 0; mf < 2; mf++)
#pragma unroll
                    for (int nf = 0; nf < 2; nf++)
                        MMAH(acc3[mf][nf], ah[mf], bh3[nf]);
            }
        }
        __syncthreads();
    }

    // epilogue
#pragma unroll
    for (int mf = 0; mf < 2; mf++) {
#pragma unroll
        for (int half = 0; half < 2; half++) {
            int mloc = wm + mf * 16 + (lane >> 2) + half * 8;
            if (routed && mloc >= rowCnt) continue;
            int sp = rowStart + mloc;
#pragma unroll
            for (int nf = 0; nf < 2; nf++) {
                float v0 = acc1[mf][nf][half * 2 + 0];
                float v1 = acc1[mf][nf][half * 2 + 1];
                int colg = by * 32 + wn + nf * 8 + (lane & 3) * 2;
                size_t o = (size_t)sp * IDIM + colg;
                if (!routed) {
                    *reinterpret_cast<__half2*>(g_Hsh + o) =
                        __floats2half2_rn(gelu_exact(v0), gelu_exact(v1));
                } else {
                    float u0 = acc3[mf][nf][half * 2 + 0];
                    float u1 = acc3[mf][nf][half * 2 + 1];
                    *reinterpret_cast<__half2*>(g_Hrh + o) =
                        __floats2half2_rn(silu_f(v0) * u0, silu_f(v1) * u1);
                }
            }
        }
    }
}

// ===================== DOWN: M128 x N64, 256 thr, 3 CTAs/SM =====================
// grid (72, 8). bx<32: out += Hsh @ sw2^T.  bx>=32: out[perm] += Hrh @ w2[e]^T.
// smem rows: A 0..127, B 128..191.
__global__ __launch_bounds__(256, 3)
void down_kernel(float* __restrict__ out)
{
    constexpr int NC = IDIM / 64;   // 32
    extern __shared__ __align__(16) char dyns[];
    __shared__ int s_rows[128];

    int bx = blockIdx.x, by = blockIdx.y;
    bool routed = (bx >= 32);
    int rowStart, rowCnt; int eid = 0;
    if (routed) {
        int bt = bx - 32;
        if (bt >= g_numTiles) return;
        eid = g_tileE[bt]; rowStart = g_tileRow[bt]; rowCnt = g_tileCnt[bt];
    } else {
        rowStart = bx * 128; rowCnt = 128;
    }

    const __half* Asrc = routed ? g_Hrh : g_Hsh;
    const __half* Bsrc = routed ? (g_w2h + (size_t)eid * (DDIM * IDIM) + (size_t)(by * 64) * IDIM)
                                : (g_sw2h + (size_t)(by * 64) * IDIM);

    int tid = threadIdx.x;
    if (tid < 128) {
        int r = routed ? min(tid, rowCnt - 1) : tid;
        s_rows[tid] = rowStart + r;
    }
    __syncthreads();

    uint32_t dynB = smem_u32(dyns);

    auto load_stage = [&](int c) {
        if (c < NC) {
            int kk = c * 64;
            uint32_t sb = dynB + (uint32_t)((c & 1) * STG);
#pragma unroll
            for (int i = 0; i < 6; i++) {
                int g = i * 256 + tid;        // 0..1535
                int row2 = g >> 3;            // 0..191
                int seg = (g & 7) * 8;
                int isB = (row2 >= 128);
                uint32_t dst = sb + (uint32_t)(row2 * (SROW * 2) + seg * 2);
                const __half* src = isB ? (Bsrc + (size_t)(row2 - 128) * IDIM + kk + seg)
                                        : (Asrc + (size_t)s_rows[row2] * IDIM + kk + seg);
                CP16(dst, src);
            }
        }
        CP_COMMIT();
    };

    int wid = tid >> 5, lane = tid & 31;
    int wm = (wid & 3) * 32;
    int wn = (wid >> 2) * 32;
    int aRow = (lane & 7) + ((lane >> 3) & 1) * 8;
    int aCol = (lane >> 4) * 8;
    int bRow = (lane & 7) + ((lane >> 4) & 1) * 8;
    int bCol = ((lane >> 3) & 1) * 8;

    float acc[2][4][4];
#pragma unroll
    for (int mf = 0; mf < 2; mf++)
#pragma unroll
        for (int nf = 0; nf < 4; nf++)
#pragma unroll
            for (int r = 0; r < 4; r++) acc[mf][nf][r] = 0.f;

    load_stage(0);

    for (int c = 0; c < NC; ++c) {
        load_stage(c + 1);
        CP_WAIT1();
        __syncthreads();
        uint32_t sbA = dynB + (uint32_t)((c & 1) * STG);
        uint32_t sbB = sbA + 128 * (SROW * 2);
#pragma unroll
        for (int kb = 0; kb < 64; kb += 16) {
            uint32_t ah[2][4], bh[4][2];
#pragma unroll
            for (int mf = 0; mf < 2; mf++) {
                uint32_t off = (uint32_t)(((wm + mf * 16 + aRow) * SROW + kb + aCol) * 2);
                LDSM4(ah[mf][0], ah[mf][1], ah[mf][2], ah[mf][3], sbA + off);
            }
#pragma unroll
            for (int n2 = 0; n2 < 2; n2++) {
                uint32_t off = (uint32_t)(((wn + n2 * 16 + bRow) * SROW + kb + bCol) * 2);
                uint32_t r0, r1, r2, r3;
                LDSM4(r0, r1, r2, r3, sbB + off);
                bh[n2 * 2][0] = r0; bh[n2 * 2][1] = r1;
                bh[n2 * 2 + 1][0] = r2; bh[n2 * 2 + 1][1] = r3;
            }
#pragma unroll
            for (int mf = 0; mf < 2; mf++)
#pragma unroll
                for (int nf = 0; nf < 4; nf++)
                    MMAH(acc[mf][nf], ah[mf], bh[nf]);
        }
        __syncthreads();
    }

#pragma unroll
    for (int mf = 0; mf < 2; mf++) {
#pragma unroll
        for (int half = 0; half < 2; half++) {
            int mloc = wm + mf * 16 + (lane >> 2) + half * 8;
            if (routed && mloc >= rowCnt) continue;
            int sp = rowStart + mloc;
            int tok = routed ? g_perm[sp] : sp;
            float* orow = out + (size_t)tok * DDIM;
#pragma unroll
            for (int nf = 0; nf < 4; nf++) {
                int colg = by * 64 + wn + nf * 8 + (lane & 3) * 2;
                atomicAdd(orow + colg,     acc[mf][nf][half * 2 + 0]);
                atomicAdd(orow + colg + 1, acc[mf][nf][half * 2 + 1]);
            }
        }
    }
}

// ===================== launch =====================
extern "C" void kernel_launch(void* const* d_in, const int* in_sizes, int n_in,
                              void* d_out, int out_size) {
    const float* x   = (const float*)d_in[0];   // [4096, 512]
    const float* gw  = (const float*)d_in[1];   // [8, 512]
    const float* w1  = (const float*)d_in[2];   // [8, 2048, 512]
    const float* w2  = (const float*)d_in[3];   // [8, 512, 2048]
    const float* w3  = (const float*)d_in[4];   // [8, 2048, 512]
    const float* sw1 = (const float*)d_in[5];   // [2048, 512]
    const float* sw2 = (const float*)d_in[6];   // [512, 2048]
    float* out = (float*)d_out;                 // [4096, 512]

    cudaMemsetAsync(out, 0, (size_t)out_size * sizeof(float));
    cvt_all<<<(int)((C_W2 + 255) / 256), 256>>>(x, sw1, sw2, w1, w3, w2);
    gate_kernel<<<NTOK / 8, 256>>>(x, gw);
    build_scatter_kernel<<<1, 256>>>();

    cudaFuncSetAttribute(up_kernel,   cudaFuncAttributeMaxDynamicSharedMemorySize, SMEMB);
    cudaFuncSetAttribute(down_kernel, cudaFuncAttributeMaxDynamicSharedMemorySize, SMEMB);

    up_kernel<<<dim3(72, IDIM / 32), 256, SMEMB>>>();
    down_kernel<<<dim3(72, DDIM / 64), 256, SMEMB>>>(out);
}

// round 16
// speedup vs baseline: 1.0614x; 1.0614x over previous
#include <cuda_runtime.h>
#include <cuda_fp16.h>
#include <math.h>
#include <stdint.h>

#define NTOK 4096
#define DDIM 512
#define IDIM 2048
#define NEXP 8
#define SROW 72                // smem row stride in halves (144 B), k-chunk 64
#define STG 36864              // 256 rows * 144 B (up: A128+B1:64+B3:64, down: A128+B128)
#define SMEMB (2 * STG)        // 73728

// ===================== device scratch =====================
__device__ int g_expert[NTOK];
__device__ int g_pos[NTOK];
__device__ int g_perm[NTOK];
__device__ int g_cnt[NEXP];
__device__ int g_off[NEXP];
__device__ int g_tileE[64];
__device__ int g_tileRow[64];
__device__ int g_tileCnt[64];
__device__ int g_numTiles;

__device__ __half g_Hsh[(size_t)NTOK * IDIM];
__device__ __half g_Hrh[(size_t)NTOK * IDIM];

__device__ __half g_xh[(size_t)NTOK * DDIM];
__device__ __half g_sw1h[(size_t)IDIM * DDIM];
__device__ __half g_sw2h[(size_t)DDIM * IDIM];
__device__ __half g_w1h[(size_t)NEXP * IDIM * DDIM];
__device__ __half g_w3h[(size_t)NEXP * IDIM * DDIM];
__device__ __half g_w2h[(size_t)NEXP * DDIM * IDIM];

// ===================== PTX helpers =====================
__device__ __forceinline__ uint32_t smem_u32(const void* p) {
    uint32_t a;
    asm("{ .reg .u64 t; cvta.to.shared.u64 t, %1; cvt.u32.u64 %0, t; }" : "=r"(a) : "l"(p));
    return a;
}
#define CP16(dst, src) asm volatile("cp.async.cg.shared.global [%0], [%1], 16;" :: "r"(dst), "l"(src))
#define CP_COMMIT()    asm volatile("cp.async.commit_group;" ::: "memory")
#define CP_WAIT1()     asm volatile("cp.async.wait_group 1;" ::: "memory")

#define LDSM4(r0, r1, r2, r3, a) \
    asm volatile("ldmatrix.sync.aligned.m8n8.x4.shared.b16 {%0,%1,%2,%3}, [%4];" \
        : "=r"(r0), "=r"(r1), "=r"(r2), "=r"(r3) : "r"(a))

#define MMAH(d, A, B) \
    asm volatile("mma.sync.aligned.m16n8k16.row.col.f32.f16.f16.f32 " \
        "{%0,%1,%2,%3},{%4,%5,%6,%7},{%8,%9},{%0,%1,%2,%3};" \
        : "+f"((d)[0]), "+f"((d)[1]), "+f"((d)[2]), "+f"((d)[3]) \
        : "r"((A)[0]), "r"((A)[1]), "r"((A)[2]), "r"((A)[3]), "r"((B)[0]), "r"((B)[1]))

// ===================== conversion + gate setup =====================
#define C_X   524288L
#define C_SW1 786432L
#define C_SW2 1048576L
#define C_W1  3145728L
#define C_W3  5242880L
#define C_W2  7340032L

__global__ void cvt_all(const float* __restrict__ x,   const float* __restrict__ sw1,
                        const float* __restrict__ sw2, const float* __restrict__ w1,
                        const float* __restrict__ w3,  const float* __restrict__ w2) {
    if (blockIdx.x == 0 && threadIdx.x < NEXP) g_cnt[threadIdx.x] = 0;
    long i = (long)blockIdx.x * blockDim.x + threadIdx.x;
    if (i >= C_W2) return;
    const float* src; __half* dst; long off;
    if (i < C_X)        { src = x;   dst = g_xh;   off = i; }
    else if (i < C_SW1) { src = sw1; dst = g_sw1h; off = i - C_X; }
    else if (i < C_SW2) { src = sw2; dst = g_sw2h; off = i - C_SW1; }
    else if (i < C_W1)  { src = w1;  dst = g_w1h;  off = i - C_SW2; }
    else if (i < C_W3)  { src = w3;  dst = g_w3h;  off = i - C_W1; }
    else                { src = w2;  dst = g_w2h;  off = i - C_W3; }
    float4 v = reinterpret_cast<const float4*>(src)[off];
    reinterpret_cast<__half2*>(dst)[off * 2 + 0] = __floats2half2_rn(v.x, v.y);
    reinterpret_cast<__half2*>(dst)[off * 2 + 1] = __floats2half2_rn(v.z, v.w);
}

__global__ void gate_kernel(const float* __restrict__ x, const float* __restrict__ gw) {
    int warp = (int)((blockIdx.x * blockDim.x + threadIdx.x) >> 5);
    int lane = threadIdx.x & 31;
    if (warp >= NTOK) return;
    const float4* xr = reinterpret_cast<const float4*>(x + (size_t)warp * DDIM + lane * 16);
    float4 xv[4];
#pragma unroll
    for (int j = 0; j < 4; j++) xv[j] = xr[j];
    float best = -1e30f; int bi = 0;
#pragma unroll
    for (int e = 0; e < NEXP; e++) {
        const float4* gr = reinterpret_cast<const float4*>(gw + (size_t)e * DDIM + lane * 16);
        float s = 0.f;
#pragma unroll
        for (int j = 0; j < 4; j++) {
            float4 g = gr[j];
            s += xv[j].x * g.x + xv[j].y * g.y + xv[j].z * g.z + xv[j].w * g.w;
        }
#pragma unroll
        for (int o = 16; o > 0; o >>= 1) s += __shfl_xor_sync(0xffffffffu, s, o);
        if (s > best) { best = s; bi = e; }
    }
    if (lane == 0) {
        g_expert[warp] = bi;
        g_pos[warp] = atomicAdd(&g_cnt[bi], 1);
    }
}

__global__ void build_scatter_kernel() {
    if (threadIdx.x == 0) {
        int off = 0;
        for (int e = 0; e < NEXP; e++) { g_off[e] = off; off += g_cnt[e]; }
        int nt = 0;
        for (int e = 0; e < NEXP; e++)
            for (int r = 0; r < g_cnt[e]; r += 128) {
                g_tileE[nt] = e;
                g_tileRow[nt] = g_off[e] + r;
                g_tileCnt[nt] = min(128, g_cnt[e] - r);
                nt++;
            }
        g_numTiles = nt;
    }
    __syncthreads();
    for (int t = threadIdx.x; t < NTOK; t += blockDim.x)
        g_perm[g_off[g_expert[t]] + g_pos[t]] = t;
}

__device__ __forceinline__ float gelu_exact(float v) {
    return 0.5f * v * (1.0f + erff(v * 0.70710678118654752f));
}
__device__ __forceinline__ float silu_f(float v) {
    return v / (1.0f + expf(-v));
}

// ===================== UP: fused shared-up + routed-up (w1&w3), 256 thr, M128xN64, k-chunk 64 =====================
// grid (72, 32). bx<32: Hsh = gelu(x @ sw1^T). bx>=32: Hrh = silu(Xg@w1^T)*(Xg@w3^T).
// smem rows: A 0..127, B1 128..191, B3 192..255.
__global__ __launch_bounds__(256, 2)
void up_kernel()
{
    constexpr int NC = DDIM / 64;   // 8
    extern __shared__ __align__(16) char dyns[];
    __shared__ int s_rows[128];

    int bx = blockIdx.x, by = blockIdx.y;
    bool routed = (bx >= 32);
    int rowStart, rowCnt; int eid = 0;
    if (routed) {
        int bt = bx - 32;
        if (bt >= g_numTiles) return;
        eid = g_tileE[bt]; rowStart = g_tileRow[bt]; rowCnt = g_tileCnt[bt];
    } else {
        rowStart = bx * 128; rowCnt = 128;
    }

    const __half* B1 = routed ? (g_w1h + (size_t)eid * (IDIM * DDIM) + (size_t)(by * 64) * DDIM)
                              : (g_sw1h + (size_t)(by * 64) * DDIM);
    const __half* B3 = g_w3h + (size_t)eid * (IDIM * DDIM) + (size_t)(by * 64) * DDIM;

    int tid = threadIdx.x;
    if (tid < 128) {
        int r = routed ? min(tid, rowCnt - 1) : tid;
        s_rows[tid] = routed ? g_perm[rowStart + r] : (rowStart + r);
    }
    __syncthreads();

    uint32_t dynB = smem_u32(dyns);

    auto load_stage = [&](int c) {
        if (c < NC) {
            int kk = c * 64;
            uint32_t sb = dynB + (uint32_t)((c & 1) * STG);
#pragma unroll
            for (int i = 0; i < 8; i++) {
                int g = i * 256 + tid;        // 0..2047
                int row = g >> 3;             // 0..255: A 0..127, B1 128..191, B3 192..255
                int seg = (g & 7) * 8;        // halves
                if (row >= 192 && !routed) continue;
                uint32_t dst = sb + (uint32_t)(row * (SROW * 2) + seg * 2);
                const __half* src;
                if (row < 128)      src = g_xh + (size_t)s_rows[row] * DDIM + kk + seg;
                else if (row < 192) src = B1 + (size_t)(row - 128) * DDIM + kk + seg;
                else                src = B3 + (size_t)(row - 192) * DDIM + kk + seg;
                CP16(dst, src);
            }
        }
        CP_COMMIT();
    };

    int wid = tid >> 5, lane = tid & 31;
    int wm = (wid & 3) * 32;
    int wn = (wid >> 2) * 32;
    int aRow = (lane & 7) + ((lane >> 3) & 1) * 8;
    int aCol = (lane >> 4) * 8;
    int bRow = (lane & 7) + ((lane >> 4) & 1) * 8;
    int bCol = ((lane >> 3) & 1) * 8;

    float acc1[2][4][4], acc3[2][4][4];
#pragma unroll
    for (int mf = 0; mf < 2; mf++)
#pragma unroll
        for (int nf = 0; nf < 4; nf++)
#pragma unroll
            for (int r = 0; r < 4; r++) { acc1[mf][nf][r] = 0.f; acc3[mf][nf][r] = 0.f; }

    load_stage(0);

    for (int c = 0; c < NC; ++c) {
        load_stage(c + 1);
        CP_WAIT1();
        __syncthreads();
        uint32_t sbA  = dynB + (uint32_t)((c & 1) * STG);
        uint32_t sbB1 = sbA + 128 * (SROW * 2);
        uint32_t sbB3 = sbA + 192 * (SROW * 2);
#pragma unroll
        for (int kb = 0; kb < 64; kb += 16) {
            uint32_t ah[2][4], bh1[4][2], bh3[4][2];
            // ALL ldmatrix first (A, B1, B3): their latencies overlap the acc1 MMA block below
#pragma unroll
            for (int mf = 0; mf < 2; mf++) {
                uint32_t off = (uint32_t)(((wm + mf * 16 + aRow) * SROW + kb + aCol) * 2);
                LDSM4(ah[mf][0], ah[mf][1], ah[mf][2], ah[mf][3], sbA + off);
            }
#pragma unroll
            for (int n2 = 0; n2 < 2; n2++) {
                uint32_t off = (uint32_t)(((wn + n2 * 16 + bRow) * SROW + kb + bCol) * 2);
                uint32_t r0, r1, r2, r3;
                LDSM4(r0, r1, r2, r3, sbB1 + off);
                bh1[n2 * 2][0] = r0; bh1[n2 * 2][1] = r1;
                bh1[n2 * 2 + 1][0] = r2; bh1[n2 * 2 + 1][1] = r3;
            }
            if (routed) {
#pragma unroll
                for (int n2 = 0; n2 < 2; n2++) {
                    uint32_t off = (uint32_t)(((wn + n2 * 16 + bRow) * SROW + kb + bCol) * 2);
                    uint32_t r0, r1, r2, r3;
                    LDSM4(r0, r1, r2, r3, sbB3 + off);
                    bh3[n2 * 2][0] = r0; bh3[n2 * 2][1] = r1;
                    bh3[n2 * 2 + 1][0] = r2; bh3[n2 * 2 + 1][1] = r3;
                }
            }
#pragma unroll
            for (int mf = 0; mf < 2; mf++)
#pragma unroll
                for (int nf = 0; nf < 4; nf++)
                    MMAH(acc1[mf][nf], ah[mf], bh1[nf]);
            if (routed) {
#pragma unroll
                for (int mf = 0; mf < 2; mf++)
#pragma unroll
                    for (int nf = 0; nf < 4; nf++)
                        MMAH(acc3[mf][nf], ah[mf], bh3[nf]);
            }
        }
        __syncthreads();
    }

    // epilogue
#pragma unroll
    for (int mf = 0; mf < 2; mf++) {
#pragma unroll
        for (int half = 0; half < 2; half++) {
            int mloc = wm + mf * 16 + (lane >> 2) + half * 8;
            if (routed && mloc >= rowCnt) continue;
            int sp = rowStart + mloc;
#pragma unroll
            for (int nf = 0; nf < 4; nf++) {
                float v0 = acc1[mf][nf][half * 2 + 0];
                float v1 = acc1[mf][nf][half * 2 + 1];
                int colg = by * 64 + wn + nf * 8 + (lane & 3) * 2;
                size_t o = (size_t)sp * IDIM + colg;
                if (!routed) {
                    *reinterpret_cast<__half2*>(g_Hsh + o) =
                        __floats2half2_rn(gelu_exact(v0), gelu_exact(v1));
                } else {
                    float u0 = acc3[mf][nf][half * 2 + 0];
                    float u1 = acc3[mf][nf][half * 2 + 1];
                    *reinterpret_cast<__half2*>(g_Hrh + o) =
                        __floats2half2_rn(silu_f(v0) * u0, silu_f(v1) * u1);
                }
            }
        }
    }
}

// ===================== DOWN: fused shared-down + routed-down, k-chunk 64 (R10 verbatim) =====================
// grid (72, 4), 256 thr. bx<32: out += Hsh @ sw2^T.  bx>=32: out[perm] += Hrh @ w2[e]^T.
__global__ __launch_bounds__(256, 2)
void down_kernel(float* __restrict__ out)
{
    constexpr int NC = IDIM / 64;   // 32
    extern __shared__ __align__(16) char dyns[];
    __shared__ int s_rows[128];

    int bx = blockIdx.x, by = blockIdx.y;
    bool routed = (bx >= 32);
    int rowStart, rowCnt; int eid = 0;
    if (routed) {
        int bt = bx - 32;
        if (bt >= g_numTiles) return;
        eid = g_tileE[bt]; rowStart = g_tileRow[bt]; rowCnt = g_tileCnt[bt];
    } else {
        rowStart = bx * 128; rowCnt = 128;
    }

    const __half* Asrc = routed ? g_Hrh : g_Hsh;
    const __half* Bsrc = routed ? (g_w2h + (size_t)eid * (DDIM * IDIM) + (size_t)(by * 128) * IDIM)
                                : (g_sw2h + (size_t)(by * 128) * IDIM);

    int tid = threadIdx.x;
    if (tid < 128) {
        int r = routed ? min(tid, rowCnt - 1) : tid;
        s_rows[tid] = rowStart + r;
    }
    __syncthreads();

    uint32_t dynB = smem_u32(dyns);

    auto load_stage = [&](int c) {
        if (c < NC) {
            int kk = c * 64;
            uint32_t sb = dynB + (uint32_t)((c & 1) * STG);
#pragma unroll
            for (int i = 0; i < 8; i++) {
                int g = i * 256 + tid;
                int row2 = g >> 3;            // 0..255
                int seg = (g & 7) * 8;
                int isB = (row2 >= 128);
                int row = row2 & 127;
                uint32_t dst = sb + (uint32_t)(row2 * (SROW * 2) + seg * 2);
                const __half* src = isB ? (Bsrc + (size_t)row * IDIM + kk + seg)
                                        : (Asrc + (size_t)s_rows[row] * IDIM + kk + seg);
                CP16(dst, src);
            }
        }
        CP_COMMIT();
    };

    int wid = tid >> 5, lane = tid & 31;
    int wm = (wid & 3) * 32;
    int wn = (wid >> 2) * 64;
    int aRow = (lane & 7) + ((lane >> 3) & 1) * 8;
    int aCol = (lane >> 4) * 8;
    int bRow = (lane & 7) + ((lane >> 4) & 1) * 8;
    int bCol = ((lane >> 3) & 1) * 8;

    float acc[2][8][4];
#pragma unroll
    for (int mf = 0; mf < 2; mf++)
#pragma unroll
        for (int nf = 0; nf < 8; nf++)
#pragma unroll
            for (int r = 0; r < 4; r++) acc[mf][nf][r] = 0.f;

    load_stage(0);

    for (int c = 0; c < NC; ++c) {
        load_stage(c + 1);
        CP_WAIT1();
        __syncthreads();
        uint32_t sbA = dynB + (uint32_t)((c & 1) * STG);
        uint32_t sbB = sbA + 128 * (SROW * 2);
#pragma unroll
        for (int kb = 0; kb < 64; kb += 16) {
            uint32_t ah[2][4], bh[8][2];
#pragma unroll
            for (int mf = 0; mf < 2; mf++) {
                uint32_t off = (uint32_t)(((wm + mf * 16 + aRow) * SROW + kb + aCol) * 2);
                LDSM4(ah[mf][0], ah[mf][1], ah[mf][2], ah[mf][3], sbA + off);
            }
#pragma unroll
            for (int n2 = 0; n2 < 4; n2++) {
                uint32_t off = (uint32_t)(((wn + n2 * 16 + bRow) * SROW + kb + bCol) * 2);
                uint32_t r0, r1, r2, r3;
                LDSM4(r0, r1, r2, r3, sbB + off);
                bh[n2 * 2][0] = r0; bh[n2 * 2][1] = r1;
                bh[n2 * 2 + 1][0] = r2; bh[n2 * 2 + 1][1] = r3;
            }
#pragma unroll
            for (int mf = 0; mf < 2; mf++)
#pragma unroll
                for (int nf = 0; nf < 8; nf++)
                    MMAH(acc[mf][nf], ah[mf], bh[nf]);
        }
        __syncthreads();
    }

#pragma unroll
    for (int mf = 0; mf < 2; mf++) {
#pragma unroll
        for (int half = 0; half < 2; half++) {
            int mloc = wm + mf * 16 + (lane >> 2) + half * 8;
            if (routed && mloc >= rowCnt) continue;
            int sp = rowStart + mloc;
            int tok = routed ? g_perm[sp] : sp;
            float* orow = out + (size_t)tok * DDIM;
#pragma unroll
            for (int nf = 0; nf < 8; nf++) {
                int colg = by * 128 + wn + nf * 8 + (lane & 3) * 2;
                atomicAdd(orow + colg,     acc[mf][nf][half * 2 + 0]);
                atomicAdd(orow + colg + 1, acc[mf][nf][half * 2 + 1]);
            }
        }
    }
}

// ===================== launch =====================
extern "C" void kernel_launch(void* const* d_in, const int* in_sizes, int n_in,
                              void* d_out, int out_size) {
    const float* x   = (const float*)d_in[0];   // [4096, 512]
    const float* gw  = (const float*)d_in[1];   // [8, 512]
    const float* w1  = (const float*)d_in[2];   // [8, 2048, 512]
    const float* w2  = (const float*)d_in[3];   // [8, 512, 2048]
    const float* w3  = (const float*)d_in[4];   // [8, 2048, 512]
    const float* sw1 = (const float*)d_in[5];   // [2048, 512]
    const float* sw2 = (const float*)d_in[6];   // [512, 2048]
    float* out = (float*)d_out;                 // [4096, 512]

    cudaMemsetAsync(out, 0, (size_t)out_size * sizeof(float));
    cvt_all<<<(int)((C_W2 + 255) / 256), 256>>>(x, sw1, sw2, w1, w3, w2);
    gate_kernel<<<NTOK / 8, 256>>>(x, gw);
    build_scatter_kernel<<<1, 256>>>();

    cudaFuncSetAttribute(up_kernel,   cudaFuncAttributeMaxDynamicSharedMemorySize, SMEMB);
    cudaFuncSetAttribute(down_kernel, cudaFuncAttributeMaxDynamicSharedMemorySize, SMEMB);

    up_kernel<<<dim3(72, IDIM / 64), 256, SMEMB>>>();
    down_kernel<<<dim3(72, DDIM / 128), 256, SMEMB>>>(out);
}

// round 17
// speedup vs baseline: 1.1198x; 1.0551x over previous
#include <cuda_runtime.h>
#include <cuda_fp16.h>
#include <math.h>
#include <stdint.h>

#define NTOK 4096
#define DDIM 512
#define IDIM 2048
#define NEXP 8
#define SROW 72                // smem row stride in halves (144 B), k-chunk 64
#define STG 36864              // 256 rows * 144 B (up: A128+B1:64+B3:64, down: A128+B128)
#define SMEMB (2 * STG)        // 73728

// ===================== device scratch =====================
__device__ int g_expert[NTOK];
__device__ int g_pos[NTOK];
__device__ int g_perm[NTOK];
__device__ int g_cnt[NEXP];
__device__ int g_off[NEXP];
__device__ int g_tileE[64];
__device__ int g_tileRow[64];
__device__ int g_tileCnt[64];
__device__ int g_numTiles;

__device__ __half g_Hsh[(size_t)NTOK * IDIM];
__device__ __half g_Hrh[(size_t)NTOK * IDIM];

__device__ __half g_xh[(size_t)NTOK * DDIM];
__device__ __half g_sw1h[(size_t)IDIM * DDIM];
__device__ __half g_sw2h[(size_t)DDIM * IDIM];
__device__ __half g_w1h[(size_t)NEXP * IDIM * DDIM];
__device__ __half g_w3h[(size_t)NEXP * IDIM * DDIM];
__device__ __half g_w2h[(size_t)NEXP * DDIM * IDIM];

// ===================== PTX helpers =====================
__device__ __forceinline__ uint32_t smem_u32(const void* p) {
    uint32_t a;
    asm("{ .reg .u64 t; cvta.to.shared.u64 t, %1; cvt.u32.u64 %0, t; }" : "=r"(a) : "l"(p));
    return a;
}
#define CP16(dst, src) asm volatile("cp.async.cg.shared.global [%0], [%1], 16;" :: "r"(dst), "l"(src))
#define CP_COMMIT()    asm volatile("cp.async.commit_group;" ::: "memory")
#define CP_WAIT1()     asm volatile("cp.async.wait_group 1;" ::: "memory")

#define LDSM4(r0, r1, r2, r3, a) \
    asm volatile("ldmatrix.sync.aligned.m8n8.x4.shared.b16 {%0,%1,%2,%3}, [%4];" \
        : "=r"(r0), "=r"(r1), "=r"(r2), "=r"(r3) : "r"(a))

#define MMAH(d, A, B) \
    asm volatile("mma.sync.aligned.m16n8k16.row.col.f32.f16.f16.f32 " \
        "{%0,%1,%2,%3},{%4,%5,%6,%7},{%8,%9},{%0,%1,%2,%3};" \
        : "+f"((d)[0]), "+f"((d)[1]), "+f"((d)[2]), "+f"((d)[3]) \
        : "r"((A)[0]), "r"((A)[1]), "r"((A)[2]), "r"((A)[3]), "r"((B)[0]), "r"((B)[1]))

// ===================== conversions =====================
// cvt_A: x, sw1, w1, w3 (inputs of up_kernel). boundaries in float4 units.
#define A_X   524288L
#define A_SW1 786432L
#define A_W1  2883584L
#define A_W3  4980736L

__global__ void cvt_A(const float* __restrict__ x,  const float* __restrict__ sw1,
                      const float* __restrict__ w1, const float* __restrict__ w3) {
    long i = (long)blockIdx.x * blockDim.x + threadIdx.x;
    if (i >= A_W3) return;
    const float* src; __half* dst; long off;
    if (i < A_X)        { src = x;   dst = g_xh;   off = i; }
    else if (i < A_SW1) { src = sw1; dst = g_sw1h; off = i - A_X; }
    else if (i < A_W1)  { src = w1;  dst = g_w1h;  off = i - A_SW1; }
    else                { src = w3;  dst = g_w3h;  off = i - A_W1; }
    float4 v = reinterpret_cast<const float4*>(src)[off];
    reinterpret_cast<__half2*>(dst)[off * 2 + 0] = __floats2half2_rn(v.x, v.y);
    reinterpret_cast<__half2*>(dst)[off * 2 + 1] = __floats2half2_rn(v.z, v.w);
}

// cvt_B: sw2, w2 (inputs of down_kernel).
#define B_SW2 262144L
#define B_W2  2359296L

__global__ void cvt_B(const float* __restrict__ sw2, const float* __restrict__ w2) {
    long i = (long)blockIdx.x * blockDim.x + threadIdx.x;
    if (i >= B_W2) return;
    const float* src; __half* dst; long off;
    if (i < B_SW2) { src = sw2; dst = g_sw2h; off = i; }
    else           { src = w2;  dst = g_w2h;  off = i - B_SW2; }
    float4 v = reinterpret_cast<const float4*>(src)[off];
    reinterpret_cast<__half2*>(dst)[off * 2 + 0] = __floats2half2_rn(v.x, v.y);
    reinterpret_cast<__half2*>(dst)[off * 2 + 1] = __floats2half2_rn(v.z, v.w);
}

__global__ void zero_kernel() {
    if (threadIdx.x < NEXP) g_cnt[threadIdx.x] = 0;
}

__global__ void gate_kernel(const float* __restrict__ x, const float* __restrict__ gw) {
    int warp = (int)((blockIdx.x * blockDim.x + threadIdx.x) >> 5);
    int lane = threadIdx.x & 31;
    if (warp >= NTOK) return;
    const float4* xr = reinterpret_cast<const float4*>(x + (size_t)warp * DDIM + lane * 16);
    float4 xv[4];
#pragma unroll
    for (int j = 0; j < 4; j++) xv[j] = xr[j];
    float best = -1e30f; int bi = 0;
#pragma unroll
    for (int e = 0; e < NEXP; e++) {
        const float4* gr = reinterpret_cast<const float4*>(gw + (size_t)e * DDIM + lane * 16);
        float s = 0.f;
#pragma unroll
        for (int j = 0; j < 4; j++) {
            float4 g = gr[j];
            s += xv[j].x * g.x + xv[j].y * g.y + xv[j].z * g.z + xv[j].w * g.w;
        }
#pragma unroll
        for (int o = 16; o > 0; o >>= 1) s += __shfl_xor_sync(0xffffffffu, s, o);
        if (s > best) { best = s; bi = e; }
    }
    if (lane == 0) {
        g_expert[warp] = bi;
        g_pos[warp] = atomicAdd(&g_cnt[bi], 1);
    }
}

__global__ void build_scatter_kernel() {
    if (threadIdx.x == 0) {
        int off = 0;
        for (int e = 0; e < NEXP; e++) { g_off[e] = off; off += g_cnt[e]; }
        int nt = 0;
        for (int e = 0; e < NEXP; e++)
            for (int r = 0; r < g_cnt[e]; r += 128) {
                g_tileE[nt] = e;
                g_tileRow[nt] = g_off[e] + r;
                g_tileCnt[nt] = min(128, g_cnt[e] - r);
                nt++;
            }
        g_numTiles = nt;
    }
    __syncthreads();
    for (int t = threadIdx.x; t < NTOK; t += blockDim.x)
        g_perm[g_off[g_expert[t]] + g_pos[t]] = t;
}

__device__ __forceinline__ float gelu_exact(float v) {
    return 0.5f * v * (1.0f + erff(v * 0.70710678118654752f));
}
__device__ __forceinline__ float silu_f(float v) {
    return v / (1.0f + expf(-v));
}

// ===================== UP: fused shared-up + routed-up (w1&w3), 256 thr, M128xN64, k-chunk 64 =====================
// grid (72, 32). bx<32: Hsh = gelu(x @ sw1^T). bx>=32: Hrh = silu(Xg@w1^T)*(Xg@w3^T).
// smem rows: A 0..127, B1 128..191, B3 192..255.  (R10 mainloop, verbatim)
__global__ __launch_bounds__(256, 2)
void up_kernel()
{
    constexpr int NC = DDIM / 64;   // 8
    extern __shared__ __align__(16) char dyns[];
    __shared__ int s_rows[128];

    int bx = blockIdx.x, by = blockIdx.y;
    bool routed = (bx >= 32);
    int rowStart, rowCnt; int eid = 0;
    if (routed) {
        int bt = bx - 32;
        if (bt >= g_numTiles) return;
        eid = g_tileE[bt]; rowStart = g_tileRow[bt]; rowCnt = g_tileCnt[bt];
    } else {
        rowStart = bx * 128; rowCnt = 128;
    }

    const __half* B1 = routed ? (g_w1h + (size_t)eid * (IDIM * DDIM) + (size_t)(by * 64) * DDIM)
                              : (g_sw1h + (size_t)(by * 64) * DDIM);
    const __half* B3 = g_w3h + (size_t)eid * (IDIM * DDIM) + (size_t)(by * 64) * DDIM;

    int tid = threadIdx.x;
    if (tid < 128) {
        int r = routed ? min(tid, rowCnt - 1) : tid;
        s_rows[tid] = routed ? g_perm[rowStart + r] : (rowStart + r);
    }
    __syncthreads();

    uint32_t dynB = smem_u32(dyns);

    auto load_stage = [&](int c) {
        if (c < NC) {
            int kk = c * 64;
            uint32_t sb = dynB + (uint32_t)((c & 1) * STG);
#pragma unroll
            for (int i = 0; i < 8; i++) {
                int g = i * 256 + tid;        // 0..2047
                int row = g >> 3;             // 0..255
                int seg = (g & 7) * 8;
                if (row >= 192 && !routed) continue;
                uint32_t dst = sb + (uint32_t)(row * (SROW * 2) + seg * 2);
                const __half* src;
                if (row < 128)      src = g_xh + (size_t)s_rows[row] * DDIM + kk + seg;
                else if (row < 192) src = B1 + (size_t)(row - 128) * DDIM + kk + seg;
                else                src = B3 + (size_t)(row - 192) * DDIM + kk + seg;
                CP16(dst, src);
            }
        }
        CP_COMMIT();
    };

    int wid = tid >> 5, lane = tid & 31;
    int wm = (wid & 3) * 32;
    int wn = (wid >> 2) * 32;
    int aRow = (lane & 7) + ((lane >> 3) & 1) * 8;
    int aCol = (lane >> 4) * 8;
    int bRow = (lane & 7) + ((lane >> 4) & 1) * 8;
    int bCol = ((lane >> 3) & 1) * 8;

    float acc1[2][4][4], acc3[2][4][4];
#pragma unroll
    for (int mf = 0; mf < 2; mf++)
#pragma unroll
        for (int nf = 0; nf < 4; nf++)
#pragma unroll
            for (int r = 0; r < 4; r++) { acc1[mf][nf][r] = 0.f; acc3[mf][nf][r] = 0.f; }

    load_stage(0);

    for (int c = 0; c < NC; ++c) {
        load_stage(c + 1);
        CP_WAIT1();
        __syncthreads();
        uint32_t sbA  = dynB + (uint32_t)((c & 1) * STG);
        uint32_t sbB1 = sbA + 128 * (SROW * 2);
        uint32_t sbB3 = sbA + 192 * (SROW * 2);
#pragma unroll
        for (int kb = 0; kb < 64; kb += 16) {
            uint32_t ah[2][4], bh1[4][2], bh3[4][2];
#pragma unroll
            for (int mf = 0; mf < 2; mf++) {
                uint32_t off = (uint32_t)(((wm + mf * 16 + aRow) * SROW + kb + aCol) * 2);
                LDSM4(ah[mf][0], ah[mf][1], ah[mf][2], ah[mf][3], sbA + off);
            }
#pragma unroll
            for (int n2 = 0; n2 < 2; n2++) {
                uint32_t off = (uint32_t)(((wn + n2 * 16 + bRow) * SROW + kb + bCol) * 2);
                uint32_t r0, r1, r2, r3;
                LDSM4(r0, r1, r2, r3, sbB1 + off);
                bh1[n2 * 2][0] = r0; bh1[n2 * 2][1] = r1;
                bh1[n2 * 2 + 1][0] = r2; bh1[n2 * 2 + 1][1] = r3;
            }
#pragma unroll
            for (int mf = 0; mf < 2; mf++)
#pragma unroll
                for (int nf = 0; nf < 4; nf++)
                    MMAH(acc1[mf][nf], ah[mf], bh1[nf]);
            if (routed) {
#pragma unroll
                for (int n2 = 0; n2 < 2; n2++) {
                    uint32_t off = (uint32_t)(((wn + n2 * 16 + bRow) * SROW + kb + bCol) * 2);
                    uint32_t r0, r1, r2, r3;
                    LDSM4(r0, r1, r2, r3, sbB3 + off);
                    bh3[n2 * 2][0] = r0; bh3[n2 * 2][1] = r1;
                    bh3[n2 * 2 + 1][0] = r2; bh3[n2 * 2 + 1][1] = r3;
                }
#pragma unroll
                for (int mf = 0; mf < 2; mf++)
#pragma unroll
                    for (int nf = 0; nf < 4; nf++)
                        MMAH(acc3[mf][nf], ah[mf], bh3[nf]);
            }
        }
        __syncthreads();
    }

    // epilogue
#pragma unroll
    for (int mf = 0; mf < 2; mf++) {
#pragma unroll
        for (int half = 0; half < 2; half++) {
            int mloc = wm + mf * 16 + (lane >> 2) + half * 8;
            if (routed && mloc >= rowCnt) continue;
            int sp = rowStart + mloc;
#pragma unroll
            for (int nf = 0; nf < 4; nf++) {
                float v0 = acc1[mf][nf][half * 2 + 0];
                float v1 = acc1[mf][nf][half * 2 + 1];
                int colg = by * 64 + wn + nf * 8 + (lane & 3) * 2;
                size_t o = (size_t)sp * IDIM + colg;
                if (!routed) {
                    *reinterpret_cast<__half2*>(g_Hsh + o) =
                        __floats2half2_rn(gelu_exact(v0), gelu_exact(v1));
                } else {
                    float u0 = acc3[mf][nf][half * 2 + 0];
                    float u1 = acc3[mf][nf][half * 2 + 1];
                    *reinterpret_cast<__half2*>(g_Hrh + o) =
                        __floats2half2_rn(silu_f(v0) * u0, silu_f(v1) * u1);
                }
            }
        }
    }
}

// ===================== DOWN: fused shared-down + routed-down, k-chunk 64 (R10 verbatim) =====================
// grid (72, 4), 256 thr. bx<32: out += Hsh @ sw2^T.  bx>=32: out[perm] += Hrh @ w2[e]^T.
__global__ __launch_bounds__(256, 2)
void down_kernel(float* __restrict__ out)
{
    constexpr int NC = IDIM / 64;   // 32
    extern __shared__ __align__(16) char dyns[];
    __shared__ int s_rows[128];

    int bx = blockIdx.x, by = blockIdx.y;
    bool routed = (bx >= 32);
    int rowStart, rowCnt; int eid = 0;
    if (routed) {
        int bt = bx - 32;
        if (bt >= g_numTiles) return;
        eid = g_tileE[bt]; rowStart = g_tileRow[bt]; rowCnt = g_tileCnt[bt];
    } else {
        rowStart = bx * 128; rowCnt = 128;
    }

    const __half* Asrc = routed ? g_Hrh : g_Hsh;
    const __half* Bsrc = routed ? (g_w2h + (size_t)eid * (DDIM * IDIM) + (size_t)(by * 128) * IDIM)
                                : (g_sw2h + (size_t)(by * 128) * IDIM);

    int tid = threadIdx.x;
    if (tid < 128) {
        int r = routed ? min(tid, rowCnt - 1) : tid;
        s_rows[tid] = rowStart + r;
    }
    __syncthreads();

    uint32_t dynB = smem_u32(dyns);

    auto load_stage = [&](int c) {
        if (c < NC) {
            int kk = c * 64;
            uint32_t sb = dynB + (uint32_t)((c & 1) * STG);
#pragma unroll
            for (int i = 0; i < 8; i++) {
                int g = i * 256 + tid;
                int row2 = g >> 3;            // 0..255
                int seg = (g & 7) * 8;
                int isB = (row2 >= 128);
                int row = row2 & 127;
                uint32_t dst = sb + (uint32_t)(row2 * (SROW * 2) + seg * 2);
                const __half* src = isB ? (Bsrc + (size_t)row * IDIM + kk + seg)
                                        : (Asrc + (size_t)s_rows[row] * IDIM + kk + seg);
                CP16(dst, src);
            }
        }
        CP_COMMIT();
    };

    int wid = tid >> 5, lane = tid & 31;
    int wm = (wid & 3) * 32;
    int wn = (wid >> 2) * 64;
    int aRow = (lane & 7) + ((lane >> 3) & 1) * 8;
    int aCol = (lane >> 4) * 8;
    int bRow = (lane & 7) + ((lane >> 4) & 1) * 8;
    int bCol = ((lane >> 3) & 1) * 8;

    float acc[2][8][4];
#pragma unroll
    for (int mf = 0; mf < 2; mf++)
#pragma unroll
        for (int nf = 0; nf < 8; nf++)
#pragma unroll
            for (int r = 0; r < 4; r++) acc[mf][nf][r] = 0.f;

    load_stage(0);

    for (int c = 0; c < NC; ++c) {
        load_stage(c + 1);
        CP_WAIT1();
        __syncthreads();
        uint32_t sbA = dynB + (uint32_t)((c & 1) * STG);
        uint32_t sbB = sbA + 128 * (SROW * 2);
#pragma unroll
        for (int kb = 0; kb < 64; kb += 16) {
            uint32_t ah[2][4], bh[8][2];
#pragma unroll
            for (int mf = 0; mf < 2; mf++) {
                uint32_t off = (uint32_t)(((wm + mf * 16 + aRow) * SROW + kb + aCol) * 2);
                LDSM4(ah[mf][0], ah[mf][1], ah[mf][2], ah[mf][3], sbA + off);
            }
#pragma unroll
            for (int n2 = 0; n2 < 4; n2++) {
                uint32_t off = (uint32_t)(((wn + n2 * 16 + bRow) * SROW + kb + bCol) * 2);
                uint32_t r0, r1, r2, r3;
                LDSM4(r0, r1, r2, r3, sbB + off);
                bh[n2 * 2][0] = r0; bh[n2 * 2][1] = r1;
                bh[n2 * 2 + 1][0] = r2; bh[n2 * 2 + 1][1] = r3;
            }
#pragma unroll
            for (int mf = 0; mf < 2; mf++)
#pragma unroll
                for (int nf = 0; nf < 8; nf++)
                    MMAH(acc[mf][nf], ah[mf], bh[nf]);
        }
        __syncthreads();
    }

#pragma unroll
    for (int mf = 0; mf < 2; mf++) {
#pragma unroll
        for (int half = 0; half < 2; half++) {
            int mloc = wm + mf * 16 + (lane >> 2) + half * 8;
            if (routed && mloc >= rowCnt) continue;
            int sp = rowStart + mloc;
            int tok = routed ? g_perm[sp] : sp;
            float* orow = out + (size_t)tok * DDIM;
#pragma unroll
            for (int nf = 0; nf < 8; nf++) {
                int colg = by * 128 + wn + nf * 8 + (lane & 3) * 2;
                atomicAdd(orow + colg,     acc[mf][nf][half * 2 + 0]);
                atomicAdd(orow + colg + 1, acc[mf][nf][half * 2 + 1]);
            }
        }
    }
}

// ===================== launch: forked-stream graph =====================
extern "C" void kernel_launch(void* const* d_in, const int* in_sizes, int n_in,
                              void* d_out, int out_size) {
    const float* x   = (const float*)d_in[0];   // [4096, 512]
    const float* gw  = (const float*)d_in[1];   // [8, 512]
    const float* w1  = (const float*)d_in[2];   // [8, 2048, 512]
    const float* w2  = (const float*)d_in[3];   // [8, 512, 2048]
    const float* w3  = (const float*)d_in[4];   // [8, 2048, 512]
    const float* sw1 = (const float*)d_in[5];   // [2048, 512]
    const float* sw2 = (const float*)d_in[6];   // [512, 2048]
    float* out = (float*)d_out;                 // [4096, 512]

    cudaFuncSetAttribute(up_kernel,   cudaFuncAttributeMaxDynamicSharedMemorySize, SMEMB);
    cudaFuncSetAttribute(down_kernel, cudaFuncAttributeMaxDynamicSharedMemorySize, SMEMB);

    // side stream + events, created per call and intentionally leaked
    // (the captured graph keeps references; only a handful of calls occur).
    cudaStream_t s1;
    cudaStreamCreateWithFlags(&s1, cudaStreamNonBlocking);
    cudaEvent_t evFork, evBuild, evTail;
    cudaEventCreateWithFlags(&evFork,  cudaEventDisableTiming);
    cudaEventCreateWithFlags(&evBuild, cudaEventDisableTiming);
    cudaEventCreateWithFlags(&evTail,  cudaEventDisableTiming);

    // fork side stream off the capture (default) stream
    cudaEventRecord(evFork, 0);
    cudaStreamWaitEvent(s1, evFork, 0);

    // side stream: routing chain, then down-only conversions + output zeroing
    zero_kernel<<<1, 32, 0, s1>>>();
    gate_kernel<<<NTOK / 8, 256, 0, s1>>>(x, gw);
    build_scatter_kernel<<<1, 256, 0, s1>>>();
    cudaEventRecord(evBuild, s1);
    cvt_B<<<(int)((B_W2 + 255) / 256), 256, 0, s1>>>(sw2, w2);
    cudaMemsetAsync(out, 0, (size_t)out_size * sizeof(float), s1);
    cudaEventRecord(evTail, s1);

    // main stream: up-side conversions, then GEMMs
    cvt_A<<<(int)((A_W3 + 255) / 256), 256>>>(x, sw1, w1, w3);
    cudaStreamWaitEvent(0, evBuild, 0);
    up_kernel<<<dim3(72, IDIM / 64), 256, SMEMB>>>();
    cudaStreamWaitEvent(0, evTail, 0);
    down_kernel<<<dim3(72, DDIM / 128), 256, SMEMB>>>(out);
}